// round 3
// baseline (speedup 1.0000x reference)
#include <cuda_runtime.h>

// Problem constants
#define BB 8
#define NN 2048
#define DD 256
#define HH 8
#define DH 32
#define ROWS (BB*NN)          // 16384
#define FF (4*DD)             // 1024
#define QK_SCALE 0.17677669529663687f   // 1/sqrt(32)

typedef unsigned long long u64;

// ---------------- packed f32x2 helpers (bitwise-exact: two fp32 ops per slot) ----
__device__ __forceinline__ u64 pack2b(float v) {            // (v, v)
    u64 r; asm("mov.b64 %0, {%1, %1};" : "=l"(r) : "f"(v)); return r;
}
__device__ __forceinline__ u64 pack2(float lo, float hi) {
    u64 r; asm("mov.b64 %0, {%1, %2};" : "=l"(r) : "f"(lo), "f"(hi)); return r;
}
__device__ __forceinline__ void unpack2(u64 v, float& lo, float& hi) {
    asm("mov.b64 {%0, %1}, %2;" : "=f"(lo), "=f"(hi) : "l"(v));
}
__device__ __forceinline__ void ffma2(u64& d, u64 a, u64 b) {   // d = a*b + d (lanewise)
    asm("fma.rn.f32x2 %0, %1, %2, %3;" : "=l"(d) : "l"(a), "l"(b), "l"(d));
}
__device__ __forceinline__ void fmul2(u64& d, u64 a) {          // d = d*a (lanewise)
    asm("mul.rn.f32x2 %0, %1, %2;" : "=l"(d) : "l"(d), "l"(a));
}

// ---------------- scratch (global, no allocation) ----------------
__device__ float g_q[BB*HH*NN*DH];     // [B,H,N,Dh]
__device__ float g_k[BB*HH*NN*DH];
__device__ float g_v[BB*HH*NN*DH];
__device__ float g_attn[ROWS*DD];      // attention out, [B,N,D]
__device__ float g_h[ROWS*DD];         // post-LN1
__device__ float g_f[ROWS*FF];         // FFN hidden
__device__ float g_g[ROWS*DD];         // h + ffn_out (pre-LN2)

// ---------------- epilogue functors ----------------
struct EpiQKV {
    const float* bias;
    __device__ void operator()(int r, int c, float acc) const {
        float val = acc + bias[c];
        int b = r >> 11, n = r & (NN - 1);
        if (c < DD) {
            int h = c >> 5, d = c & 31;
            g_q[((b*HH + h)*NN + n)*DH + d] = val;
        } else if (c < 2*DD) {
            int cc = c - DD; int h = cc >> 5, d = cc & 31;
            g_k[((b*HH + h)*NN + n)*DH + d] = val;
        } else {
            int cc = c - 2*DD; int h = cc >> 5, d = cc & 31;
            g_v[((b*HH + h)*NN + n)*DH + d] = val;
        }
    }
};

struct EpiPosAdd {   // qk_pos = pos @ Wpos + bpos; q += q_pos, k += k_pos
    const float* bias;
    __device__ void operator()(int r, int c, float acc) const {
        float val = acc + bias[c];
        int b = r >> 11, n = r & (NN - 1);
        if (c < DD) {
            int h = c >> 5, d = c & 31;
            g_q[((b*HH + h)*NN + n)*DH + d] += val;
        } else {
            int cc = c - DD; int h = cc >> 5, d = cc & 31;
            g_k[((b*HH + h)*NN + n)*DH + d] += val;
        }
    }
};

struct EpiRelu {     // FFN1: relu(h@W1 + b1) -> g_f
    const float* bias;
    __device__ void operator()(int r, int c, float acc) const {
        g_f[r*FF + c] = fmaxf(acc + bias[c], 0.0f);
    }
};

struct EpiResid {    // FFN2: g_g = (f@W2 + b2) + g_h
    const float* bias;
    __device__ void operator()(int r, int c, float acc) const {
        g_g[r*DD + c] = acc + bias[c] + g_h[r*DD + c];
    }
};

// ---------------- generic 128x128x8 fp32 GEMM (FFMA2 inner loop) ----------------
// C[r,c] = sum_k A[r,k]*W[k,c]; epilogue applied per element.
// ASRC: 0 = param pointer, 1 = g_h, 2 = g_f
template<class Epi, int ASRC>
__global__ void __launch_bounds__(256) gemm128(const float* __restrict__ Ap,
                                               const float* __restrict__ W,
                                               int M, int N, int K, Epi epi) {
    const float* __restrict__ A = (ASRC == 0) ? Ap : (ASRC == 1 ? g_h : g_f);
    __shared__ float As[8][128];
    __shared__ float Bs[8][128];
    int row0 = blockIdx.y * 128, col0 = blockIdx.x * 128;
    int tid = threadIdx.x;
    int tx = tid & 15, ty = tid >> 4;

    u64 acc[8][4];    // 8 rows x 4 packed col-pairs
#pragma unroll
    for (int i = 0; i < 8; i++)
#pragma unroll
        for (int m = 0; m < 4; m++) acc[i][m] = 0ull;

    for (int k0 = 0; k0 < K; k0 += 8) {
        // A tile: 128x8 -> As[k][row]
#pragma unroll
        for (int i = 0; i < 4; i++) {
            int e = tid * 4 + i;          // 0..1023
            int r = e >> 3, kk = e & 7;
            As[kk][r] = A[(size_t)(row0 + r) * K + k0 + kk];
        }
        // W tile: 8x128 -> Bs[k][col]
#pragma unroll
        for (int i = 0; i < 4; i++) {
            int e = tid + i * 256;        // 0..1023
            int kk = e >> 7, c = e & 127;
            Bs[kk][c] = W[(size_t)(k0 + kk) * N + col0 + c];
        }
        __syncthreads();
#pragma unroll
        for (int kk = 0; kk < 8; kk++) {
            float a[8];
            const float4* a4 = reinterpret_cast<const float4*>(&As[kk][ty * 8]);
            float4 t0 = a4[0], t1 = a4[1];
            a[0]=t0.x; a[1]=t0.y; a[2]=t0.z; a[3]=t0.w;
            a[4]=t1.x; a[5]=t1.y; a[6]=t1.z; a[7]=t1.w;
            // b as 4 packed pairs straight from smem (32B-aligned)
            const u64* bp = reinterpret_cast<const u64*>(&Bs[kk][tx * 8]);
            u64 b0 = bp[0], b1 = bp[1], b2 = bp[2], b3 = bp[3];
#pragma unroll
            for (int i = 0; i < 8; i++) {
                u64 ai = pack2b(a[i]);
                ffma2(acc[i][0], ai, b0);
                ffma2(acc[i][1], ai, b1);
                ffma2(acc[i][2], ai, b2);
                ffma2(acc[i][3], ai, b3);
            }
        }
        __syncthreads();
    }
#pragma unroll
    for (int i = 0; i < 8; i++)
#pragma unroll
        for (int m = 0; m < 4; m++) {
            float lo, hi;
            unpack2(acc[i][m], lo, hi);
            epi(row0 + ty * 8 + i, col0 + tx * 8 + 2*m,     lo);
            epi(row0 + ty * 8 + i, col0 + tx * 8 + 2*m + 1, hi);
        }
}

// ---------------- attention: 1 thread = 1 query, K/V tiles in smem ----------------
// mask is int32 (bool promoted by harness): nonzero = padded key (excluded).
__global__ void __launch_bounds__(128) attn_kernel(const int* __restrict__ mask) {
    __shared__ float Ks[64 * 32];
    __shared__ float Vs[64 * 32];
    __shared__ int Ms[64];

    int bh = blockIdx.x;              // b*8 + h
    int b = bh >> 3, h = bh & 7;
    int n = blockIdx.y * 128 + threadIdx.x;   // query index in [0,2048)

    const float* __restrict__ kbase = g_k + (size_t)bh * NN * DH;
    const float* __restrict__ vbase = g_v + (size_t)bh * NN * DH;

    u64 q2[16];     // packed (q*scale) pairs
    {
        const float4* q4 = reinterpret_cast<const float4*>(g_q + ((size_t)bh * NN + n) * DH);
#pragma unroll
        for (int i = 0; i < 8; i++) {
            float4 t = q4[i];
            q2[2*i+0] = pack2(t.x * QK_SCALE, t.y * QK_SCALE);
            q2[2*i+1] = pack2(t.z * QK_SCALE, t.w * QK_SCALE);
        }
    }
    u64 O2[16];
#pragma unroll
    for (int i = 0; i < 16; i++) O2[i] = 0ull;
    float m = -1e30f, l = 0.0f;

    const int* mrow = mask + (size_t)b * NN;

    for (int t0 = 0; t0 < NN; t0 += 64) {
        __syncthreads();
        {
            const float4* sk = reinterpret_cast<const float4*>(kbase + (size_t)t0 * DH);
            const float4* sv = reinterpret_cast<const float4*>(vbase + (size_t)t0 * DH);
            float4* dk = reinterpret_cast<float4*>(Ks);
            float4* dv = reinterpret_cast<float4*>(Vs);
#pragma unroll
            for (int i = 0; i < 4; i++) {
                int e = threadIdx.x + i * 128;   // 512 float4 total
                dk[e] = sk[e];
                dv[e] = sv[e];
            }
            if (threadIdx.x < 64) Ms[threadIdx.x] = mrow[t0 + threadIdx.x];
        }
        __syncthreads();

        for (int j = 0; j < 64; j++) {
            if (Ms[j]) continue;                 // padded key (uniform branch)
            const u64* kj = reinterpret_cast<const u64*>(Ks + j * 32);
            u64 s2 = 0ull;
#pragma unroll
            for (int i = 0; i < 16; i++) ffma2(s2, q2[i], kj[i]);
            float slo, shi;
            unpack2(s2, slo, shi);
            float s = slo + shi;

            if (s > m) {
                float f = __expf(m - s);
                m = s; l *= f;
                u64 f2 = pack2b(f);
#pragma unroll
                for (int i = 0; i < 16; i++) fmul2(O2[i], f2);
            }
            float p = __expf(s - m);
            l += p;
            u64 p2 = pack2b(p);
            const u64* vj = reinterpret_cast<const u64*>(Vs + j * 32);
#pragma unroll
            for (int i = 0; i < 16; i++) ffma2(O2[i], p2, vj[i]);
        }
    }

    float inv = 1.0f / l;
    u64 inv2 = pack2b(inv);
    u64* op = reinterpret_cast<u64*>(g_attn + ((size_t)(b * NN + n)) * DD + h * DH);
#pragma unroll
    for (int i = 0; i < 16; i++) {
        fmul2(O2[i], inv2);
        op[i] = O2[i];
    }
}

// ---------------- layernorm (1 block = 1 row of 256) ----------------
__device__ __forceinline__ float blockSum256(float v) {
    __shared__ float red[8];
#pragma unroll
    for (int o = 16; o > 0; o >>= 1) v += __shfl_xor_sync(0xffffffffu, v, o);
    int w = threadIdx.x >> 5;
    if ((threadIdx.x & 31) == 0) red[w] = v;
    __syncthreads();
    float s = 0.0f;
    if (threadIdx.x < 32) {
        s = (threadIdx.x < 8) ? red[threadIdx.x] : 0.0f;
#pragma unroll
        for (int o = 4; o > 0; o >>= 1) s += __shfl_xor_sync(0xffffffffu, s, o);
        if (threadIdx.x == 0) red[0] = s;
    }
    __syncthreads();
    float r = red[0];
    __syncthreads();   // red reused by second call
    return r;
}

// MODE 0: v = a + g_attn, result -> g_h.   MODE 1: v = g_g, result -> out.
template<int MODE>
__global__ void __launch_bounds__(256) ln_kernel(const float* __restrict__ a,
                                                 const float* __restrict__ gamma,
                                                 const float* __restrict__ beta,
                                                 float* __restrict__ out) {
    int row = blockIdx.x, t = threadIdx.x;
    size_t idx = (size_t)row * DD + t;
    float v = (MODE == 0) ? (a[idx] + g_attn[idx]) : g_g[idx];
    float mu = blockSum256(v) * (1.0f / DD);
    float d = v - mu;
    float var = blockSum256(d * d) * (1.0f / DD);
    float r = d * rsqrtf(var + 1e-5f) * gamma[t] + beta[t];
    if (MODE == 0) g_h[idx] = r;
    else           out[idx] = r;
}

// ---------------- launcher ----------------
extern "C" void kernel_launch(void* const* d_in, const int* in_sizes, int n_in,
                              void* d_out, int out_size) {
    const float* x     = (const float*)d_in[0];
    const float* pos   = (const float*)d_in[1];
    const int*   mask  = (const int*)d_in[2];
    const float* Wqkv  = (const float*)d_in[3];
    const float* bqkv  = (const float*)d_in[4];
    const float* Wpos  = (const float*)d_in[5];
    const float* bpos  = (const float*)d_in[6];
    const float* ln1g  = (const float*)d_in[7];
    const float* ln1b  = (const float*)d_in[8];
    const float* W1    = (const float*)d_in[9];
    const float* b1    = (const float*)d_in[10];
    const float* W2    = (const float*)d_in[11];
    const float* b2    = (const float*)d_in[12];
    const float* ln2g  = (const float*)d_in[13];
    const float* ln2b  = (const float*)d_in[14];
    float* out = (float*)d_out;

    // 1) qkv = x @ Wqkv + bqkv  -> scatter into g_q/g_k/g_v [B,H,N,Dh]
    gemm128<EpiQKV, 0><<<dim3(3*DD/128, ROWS/128), 256>>>(x, Wqkv, ROWS, 3*DD, DD, EpiQKV{bqkv});
    // 2) qk_pos = pos @ Wpos + bpos  -> add into g_q/g_k
    gemm128<EpiPosAdd, 0><<<dim3(2*DD/128, ROWS/128), 256>>>(pos, Wpos, ROWS, 2*DD, 2*DD, EpiPosAdd{bpos});
    // 3) masked softmax attention -> g_attn [B,N,D]
    attn_kernel<<<dim3(BB*HH, NN/128), 128>>>(mask);
    // 4) h = LN(x + attn) -> g_h
    ln_kernel<0><<<ROWS, 256>>>(x, ln1g, ln1b, out);
    // 5) f = relu(h @ W1 + b1) -> g_f
    gemm128<EpiRelu, 1><<<dim3(FF/128, ROWS/128), 256>>>(nullptr, W1, ROWS, FF, DD, EpiRelu{b1});
    // 6) g = (f @ W2 + b2) + h -> g_g
    gemm128<EpiResid, 2><<<dim3(DD/128, ROWS/128), 256>>>(nullptr, W2, ROWS, DD, FF, EpiResid{b2});
    // 7) out = LN(g)
    ln_kernel<1><<<ROWS, 256>>>(nullptr, ln2g, ln2b, out);
}

// round 6
// speedup vs baseline: 1.0011x; 1.0011x over previous
#include <cuda_runtime.h>

// Problem constants
#define BB 8
#define NN 2048
#define DD 256
#define HH 8
#define DH 32
#define ROWS (BB*NN)          // 16384
#define FF (4*DD)             // 1024
#define QK_SCALE 0.17677669529663687f   // 1/sqrt(32)

typedef unsigned long long u64;

// ---------------- packed f32x2 helpers (bitwise-exact: two fp32 ops per slot) ----
// fma.rn.f32x2 requires sm_100+, NOT 'a'-gated (unlike tcgen05) -> ok on sm_103.
__device__ __forceinline__ u64 pack2b(float v) {            // (v, v)
    u64 r; asm("mov.b64 %0, {%1, %1};" : "=l"(r) : "f"(v)); return r;
}
__device__ __forceinline__ u64 pack2(float lo, float hi) {
    u64 r; asm("mov.b64 %0, {%1, %2};" : "=l"(r) : "f"(lo), "f"(hi)); return r;
}
__device__ __forceinline__ void unpack2(u64 v, float& lo, float& hi) {
    asm("mov.b64 {%0, %1}, %2;" : "=f"(lo), "=f"(hi) : "l"(v));
}
__device__ __forceinline__ void ffma2(u64& d, u64 a, u64 b) {   // d = a*b + d (lanewise)
    asm("fma.rn.f32x2 %0, %1, %2, %3;" : "=l"(d) : "l"(a), "l"(b), "l"(d));
}
__device__ __forceinline__ void fmul2(u64& d, u64 a) {          // d = d*a (lanewise)
    asm("mul.rn.f32x2 %0, %1, %2;" : "=l"(d) : "l"(d), "l"(a));
}

// ---------------- scratch (global, no allocation) ----------------
__device__ float g_q[BB*HH*NN*DH];     // [B,H,N,Dh]
__device__ float g_k[BB*HH*NN*DH];
__device__ float g_v[BB*HH*NN*DH];
__device__ float g_attn[ROWS*DD];      // attention out, [B,N,D]
__device__ float g_h[ROWS*DD];         // post-LN1
__device__ float g_f[ROWS*FF];         // FFN hidden
__device__ float g_g[ROWS*DD];         // h + ffn_out (pre-LN2)

// ---------------- epilogue functors ----------------
struct EpiQKV {
    const float* bias;
    __device__ void operator()(int r, int c, float acc) const {
        float val = acc + bias[c];
        int b = r >> 11, n = r & (NN - 1);
        if (c < DD) {
            int h = c >> 5, d = c & 31;
            g_q[((b*HH + h)*NN + n)*DH + d] = val;
        } else if (c < 2*DD) {
            int cc = c - DD; int h = cc >> 5, d = cc & 31;
            g_k[((b*HH + h)*NN + n)*DH + d] = val;
        } else {
            int cc = c - 2*DD; int h = cc >> 5, d = cc & 31;
            g_v[((b*HH + h)*NN + n)*DH + d] = val;
        }
    }
};

struct EpiPosAdd {   // qk_pos = pos @ Wpos + bpos; q += q_pos, k += k_pos
    const float* bias;
    __device__ void operator()(int r, int c, float acc) const {
        float val = acc + bias[c];
        int b = r >> 11, n = r & (NN - 1);
        if (c < DD) {
            int h = c >> 5, d = c & 31;
            g_q[((b*HH + h)*NN + n)*DH + d] += val;
        } else {
            int cc = c - DD; int h = cc >> 5, d = cc & 31;
            g_k[((b*HH + h)*NN + n)*DH + d] += val;
        }
    }
};

struct EpiRelu {     // FFN1: relu(h@W1 + b1) -> g_f
    const float* bias;
    __device__ void operator()(int r, int c, float acc) const {
        g_f[r*FF + c] = fmaxf(acc + bias[c], 0.0f);
    }
};

struct EpiResid {    // FFN2: g_g = (f@W2 + b2) + g_h
    const float* bias;
    __device__ void operator()(int r, int c, float acc) const {
        g_g[r*DD + c] = acc + bias[c] + g_h[r*DD + c];
    }
};

// ---------------- generic 128x128x8 fp32 GEMM (FFMA2 inner loop) ----------------
// C[r,c] = sum_k A[r,k]*W[k,c]; epilogue applied per element.
// ASRC: 0 = param pointer, 1 = g_h, 2 = g_f
template<class Epi, int ASRC>
__global__ void __launch_bounds__(256) gemm128(const float* __restrict__ Ap,
                                               const float* __restrict__ W,
                                               int M, int N, int K, Epi epi) {
    const float* __restrict__ A = (ASRC == 0) ? Ap : (ASRC == 1 ? g_h : g_f);
    __shared__ float As[8][128];
    __shared__ float Bs[8][128];
    int row0 = blockIdx.y * 128, col0 = blockIdx.x * 128;
    int tid = threadIdx.x;
    int tx = tid & 15, ty = tid >> 4;

    u64 acc[8][4];    // 8 rows x 4 packed col-pairs
#pragma unroll
    for (int i = 0; i < 8; i++)
#pragma unroll
        for (int m = 0; m < 4; m++) acc[i][m] = 0ull;

    for (int k0 = 0; k0 < K; k0 += 8) {
        // A tile: 128x8 -> As[k][row]
#pragma unroll
        for (int i = 0; i < 4; i++) {
            int e = tid * 4 + i;          // 0..1023
            int r = e >> 3, kk = e & 7;
            As[kk][r] = A[(size_t)(row0 + r) * K + k0 + kk];
        }
        // W tile: 8x128 -> Bs[k][col]
#pragma unroll
        for (int i = 0; i < 4; i++) {
            int e = tid + i * 256;        // 0..1023
            int kk = e >> 7, c = e & 127;
            Bs[kk][c] = W[(size_t)(k0 + kk) * N + col0 + c];
        }
        __syncthreads();
#pragma unroll
        for (int kk = 0; kk < 8; kk++) {
            float a[8];
            const float4* a4 = reinterpret_cast<const float4*>(&As[kk][ty * 8]);
            float4 t0 = a4[0], t1 = a4[1];
            a[0]=t0.x; a[1]=t0.y; a[2]=t0.z; a[3]=t0.w;
            a[4]=t1.x; a[5]=t1.y; a[6]=t1.z; a[7]=t1.w;
            // b as 4 packed pairs straight from smem (32B-aligned)
            const u64* bp = reinterpret_cast<const u64*>(&Bs[kk][tx * 8]);
            u64 b0 = bp[0], b1 = bp[1], b2 = bp[2], b3 = bp[3];
#pragma unroll
            for (int i = 0; i < 8; i++) {
                u64 ai = pack2b(a[i]);
                ffma2(acc[i][0], ai, b0);
                ffma2(acc[i][1], ai, b1);
                ffma2(acc[i][2], ai, b2);
                ffma2(acc[i][3], ai, b3);
            }
        }
        __syncthreads();
    }
#pragma unroll
    for (int i = 0; i < 8; i++)
#pragma unroll
        for (int m = 0; m < 4; m++) {
            float lo, hi;
            unpack2(acc[i][m], lo, hi);
            epi(row0 + ty * 8 + i, col0 + tx * 8 + 2*m,     lo);
            epi(row0 + ty * 8 + i, col0 + tx * 8 + 2*m + 1, hi);
        }
}

// ---------------- attention: 1 thread = 1 query, K/V tiles in smem ----------------
// mask is int32 (bool promoted by harness): nonzero = padded key (excluded).
__global__ void __launch_bounds__(128) attn_kernel(const int* __restrict__ mask) {
    __shared__ float Ks[64 * 32];
    __shared__ float Vs[64 * 32];
    __shared__ int Ms[64];

    int bh = blockIdx.x;              // b*8 + h
    int b = bh >> 3, h = bh & 7;
    int n = blockIdx.y * 128 + threadIdx.x;   // query index in [0,2048)

    const float* __restrict__ kbase = g_k + (size_t)bh * NN * DH;
    const float* __restrict__ vbase = g_v + (size_t)bh * NN * DH;

    u64 q2[16];     // packed (q*scale) pairs
    {
        const float4* q4 = reinterpret_cast<const float4*>(g_q + ((size_t)bh * NN + n) * DH);
#pragma unroll
        for (int i = 0; i < 8; i++) {
            float4 t = q4[i];
            q2[2*i+0] = pack2(t.x * QK_SCALE, t.y * QK_SCALE);
            q2[2*i+1] = pack2(t.z * QK_SCALE, t.w * QK_SCALE);
        }
    }
    u64 O2[16];
#pragma unroll
    for (int i = 0; i < 16; i++) O2[i] = 0ull;
    float m = -1e30f, l = 0.0f;

    const int* mrow = mask + (size_t)b * NN;

    for (int t0 = 0; t0 < NN; t0 += 64) {
        __syncthreads();
        {
            const float4* sk = reinterpret_cast<const float4*>(kbase + (size_t)t0 * DH);
            const float4* sv = reinterpret_cast<const float4*>(vbase + (size_t)t0 * DH);
            float4* dk = reinterpret_cast<float4*>(Ks);
            float4* dv = reinterpret_cast<float4*>(Vs);
#pragma unroll
            for (int i = 0; i < 4; i++) {
                int e = threadIdx.x + i * 128;   // 512 float4 total
                dk[e] = sk[e];
                dv[e] = sv[e];
            }
            if (threadIdx.x < 64) Ms[threadIdx.x] = mrow[t0 + threadIdx.x];
        }
        __syncthreads();

        for (int j = 0; j < 64; j++) {
            if (Ms[j]) continue;                 // padded key (uniform branch)
            const u64* kj = reinterpret_cast<const u64*>(Ks + j * 32);
            u64 s2 = 0ull;
#pragma unroll
            for (int i = 0; i < 16; i++) ffma2(s2, q2[i], kj[i]);
            float slo, shi;
            unpack2(s2, slo, shi);
            float s = slo + shi;

            if (s > m) {
                float f = __expf(m - s);
                m = s; l *= f;
                u64 f2 = pack2b(f);
#pragma unroll
                for (int i = 0; i < 16; i++) fmul2(O2[i], f2);
            }
            float p = __expf(s - m);
            l += p;
            u64 p2 = pack2b(p);
            const u64* vj = reinterpret_cast<const u64*>(Vs + j * 32);
#pragma unroll
            for (int i = 0; i < 16; i++) ffma2(O2[i], p2, vj[i]);
        }
    }

    float inv = 1.0f / l;
    u64 inv2 = pack2b(inv);
    u64* op = reinterpret_cast<u64*>(g_attn + ((size_t)(b * NN + n)) * DD + h * DH);
#pragma unroll
    for (int i = 0; i < 16; i++) {
        fmul2(O2[i], inv2);
        op[i] = O2[i];
    }
}

// ---------------- layernorm (1 block = 1 row of 256) ----------------
__device__ __forceinline__ float blockSum256(float v) {
    __shared__ float red[8];
#pragma unroll
    for (int o = 16; o > 0; o >>= 1) v += __shfl_xor_sync(0xffffffffu, v, o);
    int w = threadIdx.x >> 5;
    if ((threadIdx.x & 31) == 0) red[w] = v;
    __syncthreads();
    float s = 0.0f;
    if (threadIdx.x < 32) {
        s = (threadIdx.x < 8) ? red[threadIdx.x] : 0.0f;
#pragma unroll
        for (int o = 4; o > 0; o >>= 1) s += __shfl_xor_sync(0xffffffffu, s, o);
        if (threadIdx.x == 0) red[0] = s;
    }
    __syncthreads();
    float r = red[0];
    __syncthreads();   // red reused by second call
    return r;
}

// MODE 0: v = a + g_attn, result -> g_h.   MODE 1: v = g_g, result -> out.
template<int MODE>
__global__ void __launch_bounds__(256) ln_kernel(const float* __restrict__ a,
                                                 const float* __restrict__ gamma,
                                                 const float* __restrict__ beta,
                                                 float* __restrict__ out) {
    int row = blockIdx.x, t = threadIdx.x;
    size_t idx = (size_t)row * DD + t;
    float v = (MODE == 0) ? (a[idx] + g_attn[idx]) : g_g[idx];
    float mu = blockSum256(v) * (1.0f / DD);
    float d = v - mu;
    float var = blockSum256(d * d) * (1.0f / DD);
    float r = d * rsqrtf(var + 1e-5f) * gamma[t] + beta[t];
    if (MODE == 0) g_h[idx] = r;
    else           out[idx] = r;
}

// ---------------- launcher ----------------
extern "C" void kernel_launch(void* const* d_in, const int* in_sizes, int n_in,
                              void* d_out, int out_size) {
    const float* x     = (const float*)d_in[0];
    const float* pos   = (const float*)d_in[1];
    const int*   mask  = (const int*)d_in[2];
    const float* Wqkv  = (const float*)d_in[3];
    const float* bqkv  = (const float*)d_in[4];
    const float* Wpos  = (const float*)d_in[5];
    const float* bpos  = (const float*)d_in[6];
    const float* ln1g  = (const float*)d_in[7];
    const float* ln1b  = (const float*)d_in[8];
    const float* W1    = (const float*)d_in[9];
    const float* b1    = (const float*)d_in[10];
    const float* W2    = (const float*)d_in[11];
    const float* b2    = (const float*)d_in[12];
    const float* ln2g  = (const float*)d_in[13];
    const float* ln2b  = (const float*)d_in[14];
    float* out = (float*)d_out;

    // 1) qkv = x @ Wqkv + bqkv  -> scatter into g_q/g_k/g_v [B,H,N,Dh]
    gemm128<EpiQKV, 0><<<dim3(3*DD/128, ROWS/128), 256>>>(x, Wqkv, ROWS, 3*DD, DD, EpiQKV{bqkv});
    // 2) qk_pos = pos @ Wpos + bpos  -> add into g_q/g_k
    gemm128<EpiPosAdd, 0><<<dim3(2*DD/128, ROWS/128), 256>>>(pos, Wpos, ROWS, 2*DD, 2*DD, EpiPosAdd{bpos});
    // 3) masked softmax attention -> g_attn [B,N,D]
    attn_kernel<<<dim3(BB*HH, NN/128), 128>>>(mask);
    // 4) h = LN(x + attn) -> g_h
    ln_kernel<0><<<ROWS, 256>>>(x, ln1g, ln1b, out);
    // 5) f = relu(h @ W1 + b1) -> g_f
    gemm128<EpiRelu, 1><<<dim3(FF/128, ROWS/128), 256>>>(nullptr, W1, ROWS, FF, DD, EpiRelu{b1});
    // 6) g = (f @ W2 + b2) + h -> g_g
    gemm128<EpiResid, 2><<<dim3(DD/128, ROWS/128), 256>>>(nullptr, W2, ROWS, DD, FF, EpiResid{b2});
    // 7) out = LN(g)
    ln_kernel<1><<<ROWS, 256>>>(nullptr, ln2g, ln2b, out);
}

// round 9
// speedup vs baseline: 1.1395x; 1.1382x over previous
#include <cuda_runtime.h>

// Problem constants
#define BB 8
#define NN 2048
#define DD 256
#define HH 8
#define DH 32
#define ROWS (BB*NN)          // 16384
#define FF (4*DD)             // 1024
#define QK_SCALE 0.17677669529663687f   // 1/sqrt(32)

typedef unsigned long long u64;
typedef unsigned int u32;

// ---------------- packed f32x2 helpers (bitwise-exact fp32 pairs) ----------------
__device__ __forceinline__ u64 pack2b(float v) {
    u64 r; asm("mov.b64 %0, {%1, %1};" : "=l"(r) : "f"(v)); return r;
}
__device__ __forceinline__ u64 pack2(float lo, float hi) {
    u64 r; asm("mov.b64 %0, {%1, %2};" : "=l"(r) : "f"(lo), "f"(hi)); return r;
}
__device__ __forceinline__ void unpack2(u64 v, float& lo, float& hi) {
    asm("mov.b64 {%0, %1}, %2;" : "=f"(lo), "=f"(hi) : "l"(v));
}
__device__ __forceinline__ void ffma2(u64& d, u64 a, u64 b) {
    asm("fma.rn.f32x2 %0, %1, %2, %3;" : "=l"(d) : "l"(a), "l"(b), "l"(d));
}
__device__ __forceinline__ void fmul2(u64& d, u64 a) {
    asm("mul.rn.f32x2 %0, %1, %2;" : "=l"(d) : "l"(d), "l"(a));
}

// ---------------- cp.async helpers (sm_80+, not arch-variant) ----------------
__device__ __forceinline__ u32 smem_u32(const void* p) {
    u32 a; asm("{ .reg .u64 t; cvta.to.shared.u64 t, %1; cvt.u32.u64 %0, t; }" : "=r"(a) : "l"(p));
    return a;
}
#define CP_ASYNC16(smem, gmem) \
    asm volatile("cp.async.cg.shared.global [%0], [%1], 16;" :: "r"(smem), "l"(gmem) : "memory")
#define CP_COMMIT() asm volatile("cp.async.commit_group;" ::: "memory")
#define CP_WAIT(n)  asm volatile("cp.async.wait_group %0;" :: "n"(n) : "memory")

// ---------------- scratch (global, no allocation) ----------------
__device__ float g_q[BB*HH*NN*DH];     // [B,H,N,Dh]
__device__ float g_k[BB*HH*NN*DH];
__device__ float g_v[BB*HH*NN*DH];
__device__ float g_attn[ROWS*DD];      // attention out, [B,N,D]
__device__ float g_h[ROWS*DD];         // post-LN1
__device__ float g_f[ROWS*FF];         // FFN hidden
__device__ float g_g[ROWS*DD];         // h + ffn_out (pre-LN2)

// ---------------- epilogue functors ----------------
struct EpiQKV {
    const float* bias;
    __device__ void operator()(int r, int c, float acc) const {
        float val = acc + bias[c];
        int b = r >> 11, n = r & (NN - 1);
        if (c < DD) {
            int h = c >> 5, d = c & 31;
            g_q[((b*HH + h)*NN + n)*DH + d] = val;
        } else if (c < 2*DD) {
            int cc = c - DD; int h = cc >> 5, d = cc & 31;
            g_k[((b*HH + h)*NN + n)*DH + d] = val;
        } else {
            int cc = c - 2*DD; int h = cc >> 5, d = cc & 31;
            g_v[((b*HH + h)*NN + n)*DH + d] = val;
        }
    }
};

struct EpiPosAdd {
    const float* bias;
    __device__ void operator()(int r, int c, float acc) const {
        float val = acc + bias[c];
        int b = r >> 11, n = r & (NN - 1);
        if (c < DD) {
            int h = c >> 5, d = c & 31;
            g_q[((b*HH + h)*NN + n)*DH + d] += val;
        } else {
            int cc = c - DD; int h = cc >> 5, d = cc & 31;
            g_k[((b*HH + h)*NN + n)*DH + d] += val;
        }
    }
};

struct EpiRelu {
    const float* bias;
    __device__ void operator()(int r, int c, float acc) const {
        g_f[r*FF + c] = fmaxf(acc + bias[c], 0.0f);
    }
};

struct EpiResid {
    const float* bias;
    __device__ void operator()(int r, int c, float acc) const {
        g_g[r*DD + c] = acc + bias[c] + g_h[r*DD + c];
    }
};

// ---------------- 128x128x8 fp32 GEMM, double-buffered pipeline ----------------
// A tile: LDG.128 register prefetch + STS (transposed to As[kk][row]).
// B tile: cp.async 16B per thread into Bs[kk][col].
// ASRC: 0 = param pointer, 1 = g_h, 2 = g_f
template<class Epi, int ASRC>
__global__ void __launch_bounds__(256) gemm128(const float* __restrict__ Ap,
                                               const float* __restrict__ W,
                                               int N, int K, Epi epi) {
    const float* __restrict__ A = (ASRC == 0) ? Ap : (ASRC == 1 ? g_h : g_f);
    __shared__ float As[2][8][128];
    __shared__ float Bs[2][8][128];
    int row0 = blockIdx.y * 128, col0 = blockIdx.x * 128;
    int tid = threadIdx.x;
    int tx = tid & 15, ty = tid >> 4;

    // A mapping: e = tid*4 -> row = e>>3, kk0 = e&7 (0 or 4), 4 consecutive k
    int ar = (tid * 4) >> 3, ak = (tid * 4) & 7;
    // B mapping: kk = tid>>5 (0..7), col chunk c = (tid&31)*4
    int bk = tid >> 5, bc = (tid & 31) * 4;

    u64 acc[8][4];
#pragma unroll
    for (int i = 0; i < 8; i++)
#pragma unroll
        for (int m = 0; m < 4; m++) acc[i][m] = 0ull;

    const int KT = K >> 3;

    // ---- preload stage 0 ----
    float4 aReg = *reinterpret_cast<const float4*>(&A[(size_t)(row0 + ar) * K + ak]);
    CP_ASYNC16(smem_u32(&Bs[0][bk][bc]), &W[(size_t)bk * N + col0 + bc]);
    CP_COMMIT();
    As[0][ak + 0][ar] = aReg.x;
    As[0][ak + 1][ar] = aReg.y;
    As[0][ak + 2][ar] = aReg.z;
    As[0][ak + 3][ar] = aReg.w;
    CP_WAIT(0);
    __syncthreads();

    for (int kt = 0; kt < KT; kt++) {
        int nxt = kt + 1;
        if (nxt < KT) {
            int k0 = nxt * 8;
            aReg = *reinterpret_cast<const float4*>(&A[(size_t)(row0 + ar) * K + k0 + ak]);
            CP_ASYNC16(smem_u32(&Bs[nxt & 1][bk][bc]), &W[(size_t)(k0 + bk) * N + col0 + bc]);
            CP_COMMIT();
        }
        // ---- compute current tile ----
        int cur = kt & 1;
#pragma unroll
        for (int kk = 0; kk < 8; kk++) {
            float a[8];
            const float4* a4 = reinterpret_cast<const float4*>(&As[cur][kk][ty * 8]);
            float4 t0 = a4[0], t1 = a4[1];
            a[0]=t0.x; a[1]=t0.y; a[2]=t0.z; a[3]=t0.w;
            a[4]=t1.x; a[5]=t1.y; a[6]=t1.z; a[7]=t1.w;
            const u64* bp = reinterpret_cast<const u64*>(&Bs[cur][kk][tx * 8]);
            u64 b0 = bp[0], b1 = bp[1], b2 = bp[2], b3 = bp[3];
#pragma unroll
            for (int i = 0; i < 8; i++) {
                u64 ai = pack2b(a[i]);
                ffma2(acc[i][0], ai, b0);
                ffma2(acc[i][1], ai, b1);
                ffma2(acc[i][2], ai, b2);
                ffma2(acc[i][3], ai, b3);
            }
        }
        __syncthreads();               // all warps done reading tile kt
        if (nxt < KT) {
            int nb = nxt & 1;
            As[nb][ak + 0][ar] = aReg.x;
            As[nb][ak + 1][ar] = aReg.y;
            As[nb][ak + 2][ar] = aReg.z;
            As[nb][ak + 3][ar] = aReg.w;
            CP_WAIT(0);                // B(nxt) landed (this thread)
            __syncthreads();           // tile nxt globally ready
        }
    }

#pragma unroll
    for (int i = 0; i < 8; i++)
#pragma unroll
        for (int m = 0; m < 4; m++) {
            float lo, hi;
            unpack2(acc[i][m], lo, hi);
            epi(row0 + ty * 8 + i, col0 + tx * 8 + 2*m,     lo);
            epi(row0 + ty * 8 + i, col0 + tx * 8 + 2*m + 1, hi);
        }
}

// ---------------- attention: 1 thread = 1 query, cp.async double-buffered tiles ----
// mask is int32 (bool promoted by harness): nonzero = padded key (excluded).
__global__ void __launch_bounds__(128) attn_kernel(const int* __restrict__ mask) {
    __shared__ float Ks[2][64 * 32];
    __shared__ float Vs[2][64 * 32];
    __shared__ int Ms[2][64];

    int bh = blockIdx.x;              // b*8 + h
    int b = bh >> 3, h = bh & 7;
    int t = threadIdx.x;
    int n = blockIdx.y * 128 + t;     // query index

    const float* __restrict__ kbase = g_k + (size_t)bh * NN * DH;
    const float* __restrict__ vbase = g_v + (size_t)bh * NN * DH;
    const int* mrow = mask + (size_t)b * NN;

    u64 q2[16];
    {
        const float4* q4 = reinterpret_cast<const float4*>(g_q + ((size_t)bh * NN + n) * DH);
#pragma unroll
        for (int i = 0; i < 8; i++) {
            float4 tq = q4[i];
            q2[2*i+0] = pack2(tq.x * QK_SCALE, tq.y * QK_SCALE);
            q2[2*i+1] = pack2(tq.z * QK_SCALE, tq.w * QK_SCALE);
        }
    }
    u64 O2[16];
#pragma unroll
    for (int i = 0; i < 16; i++) O2[i] = 0ull;
    float m = -1e30f, l = 0.0f;

    const int NT = NN / 64;   // 32 tiles

    // tile issue: 64*32 floats = 512 float4 per array; 4 chunks/thread each
    auto issue_tile = [&](int ti, int buf) {
        const float* ks = kbase + (size_t)ti * 64 * DH;
        const float* vs = vbase + (size_t)ti * 64 * DH;
#pragma unroll
        for (int i = 0; i < 4; i++) {
            int e = (t + i * 128) * 4;
            CP_ASYNC16(smem_u32(&Ks[buf][e]), ks + e);
            CP_ASYNC16(smem_u32(&Vs[buf][e]), vs + e);
        }
        if (t < 16) CP_ASYNC16(smem_u32(&Ms[buf][t * 4]), mrow + ti * 64 + t * 4);
        CP_COMMIT();
    };

    issue_tile(0, 0);

    for (int tt = 0; tt < NT; tt++) {
        if (tt + 1 < NT) {
            issue_tile(tt + 1, (tt + 1) & 1);   // overwrites buf read at tt-1 (guarded by end-bar)
            CP_WAIT(1);                          // tile tt complete
        } else {
            CP_WAIT(0);
        }
        __syncthreads();

        int cur = tt & 1;
        for (int j = 0; j < 64; j++) {
            if (Ms[cur][j]) continue;            // padded key (uniform)
            const u64* kj = reinterpret_cast<const u64*>(&Ks[cur][j * 32]);
            u64 s2 = 0ull;
#pragma unroll
            for (int i = 0; i < 16; i++) ffma2(s2, q2[i], kj[i]);
            float slo, shi;
            unpack2(s2, slo, shi);
            float s = slo + shi;

            if (s > m) {
                float f = __expf(m - s);
                m = s; l *= f;
                u64 f2 = pack2b(f);
#pragma unroll
                for (int i = 0; i < 16; i++) fmul2(O2[i], f2);
            }
            float p = __expf(s - m);
            l += p;
            u64 p2 = pack2b(p);
            const u64* vj = reinterpret_cast<const u64*>(&Vs[cur][j * 32]);
#pragma unroll
            for (int i = 0; i < 16; i++) ffma2(O2[i], p2, vj[i]);
        }
        __syncthreads();                         // all done reading tile tt (buffer reuse guard)
    }

    float inv = 1.0f / l;
    u64 inv2 = pack2b(inv);
    u64* op = reinterpret_cast<u64*>(g_attn + ((size_t)(b * NN + n)) * DD + h * DH);
#pragma unroll
    for (int i = 0; i < 16; i++) {
        fmul2(O2[i], inv2);
        op[i] = O2[i];
    }
}

// ---------------- layernorm (1 block = 1 row of 256) ----------------
__device__ __forceinline__ float blockSum256(float v) {
    __shared__ float red[8];
#pragma unroll
    for (int o = 16; o > 0; o >>= 1) v += __shfl_xor_sync(0xffffffffu, v, o);
    int w = threadIdx.x >> 5;
    if ((threadIdx.x & 31) == 0) red[w] = v;
    __syncthreads();
    float s = 0.0f;
    if (threadIdx.x < 32) {
        s = (threadIdx.x < 8) ? red[threadIdx.x] : 0.0f;
#pragma unroll
        for (int o = 4; o > 0; o >>= 1) s += __shfl_xor_sync(0xffffffffu, s, o);
        if (threadIdx.x == 0) red[0] = s;
    }
    __syncthreads();
    float r = red[0];
    __syncthreads();
    return r;
}

// MODE 0: v = a + g_attn, result -> g_h.   MODE 1: v = g_g, result -> out.
template<int MODE>
__global__ void __launch_bounds__(256) ln_kernel(const float* __restrict__ a,
                                                 const float* __restrict__ gamma,
                                                 const float* __restrict__ beta,
                                                 float* __restrict__ out) {
    int row = blockIdx.x, t = threadIdx.x;
    size_t idx = (size_t)row * DD + t;
    float v = (MODE == 0) ? (a[idx] + g_attn[idx]) : g_g[idx];
    float mu = blockSum256(v) * (1.0f / DD);
    float d = v - mu;
    float var = blockSum256(d * d) * (1.0f / DD);
    float r = d * rsqrtf(var + 1e-5f) * gamma[t] + beta[t];
    if (MODE == 0) g_h[idx] = r;
    else           out[idx] = r;
}

// ---------------- launcher ----------------
extern "C" void kernel_launch(void* const* d_in, const int* in_sizes, int n_in,
                              void* d_out, int out_size) {
    const float* x     = (const float*)d_in[0];
    const float* pos   = (const float*)d_in[1];
    const int*   mask  = (const int*)d_in[2];
    const float* Wqkv  = (const float*)d_in[3];
    const float* bqkv  = (const float*)d_in[4];
    const float* Wpos  = (const float*)d_in[5];
    const float* bpos  = (const float*)d_in[6];
    const float* ln1g  = (const float*)d_in[7];
    const float* ln1b  = (const float*)d_in[8];
    const float* W1    = (const float*)d_in[9];
    const float* b1    = (const float*)d_in[10];
    const float* W2    = (const float*)d_in[11];
    const float* b2    = (const float*)d_in[12];
    const float* ln2g  = (const float*)d_in[13];
    const float* ln2b  = (const float*)d_in[14];
    float* out = (float*)d_out;

    // 1) qkv = x @ Wqkv + bqkv -> g_q/g_k/g_v [B,H,N,Dh]
    gemm128<EpiQKV, 0><<<dim3(3*DD/128, ROWS/128), 256>>>(x, Wqkv, 3*DD, DD, EpiQKV{bqkv});
    // 2) qk_pos = pos @ Wpos + bpos -> add into g_q/g_k
    gemm128<EpiPosAdd, 0><<<dim3(2*DD/128, ROWS/128), 256>>>(pos, Wpos, 2*DD, 2*DD, EpiPosAdd{bpos});
    // 3) masked softmax attention -> g_attn [B,N,D]
    attn_kernel<<<dim3(BB*HH, NN/128), 128>>>(mask);
    // 4) h = LN(x + attn) -> g_h
    ln_kernel<0><<<ROWS, 256>>>(x, ln1g, ln1b, out);
    // 5) f = relu(h @ W1 + b1) -> g_f
    gemm128<EpiRelu, 1><<<dim3(FF/128, ROWS/128), 256>>>(nullptr, W1, FF, DD, EpiRelu{b1});
    // 6) g = (f @ W2 + b2) + h -> g_g
    gemm128<EpiResid, 2><<<dim3(DD/128, ROWS/128), 256>>>(nullptr, W2, DD, FF, EpiResid{b2});
    // 7) out = LN(g)
    ln_kernel<1><<<ROWS, 256>>>(nullptr, ln2g, ln2b, out);
}